// round 4
// baseline (speedup 1.0000x reference)
#include <cuda_runtime.h>
#include <cuda_bf16.h>
#include <math.h>

#define T_LEN 512
#define B_SZ  128
#define D_IN  256
#define U_SZ  256
#define NG    768
#define WHS 260
#define HSS 260
#define BG_CTAS 32
#define SCAN_CTAS 128
#define PROJ_CTAS 3072      // 512 t-tiles x 6 n-tiles

// ---------------- scratch ----------------
__device__ float    g_x  [T_LEN * B_SZ * U_SZ];
__device__ float    g_xp0[T_LEN * B_SZ * NG];
__device__ float    g_xp1[T_LEN * B_SZ * NG];
__device__ float    g_h  [2][B_SZ * U_SZ];
__device__ unsigned g_bar[4 * T_LEN * 4];        // [layer][t][bg]

// ---------------- embedding ----------------
__global__ void embed_kernel(const int* __restrict__ tokens, const float* __restrict__ emb) {
    int gid = blockIdx.x * blockDim.x + threadIdx.x;
    int row = gid >> 6;
    int c4  = gid & 63;
    int t = row >> 7;
    int b = row & 127;
    int tok = tokens[b * T_LEN + t];
    const float4* e4 = reinterpret_cast<const float4*>(emb);
    float4*       x4 = reinterpret_cast<float4*>(g_x);
    x4[(size_t)row * 64 + c4] = e4[(size_t)tok * 64 + c4];
}

// ---------------- proj GEMM body (shared by standalone + fused) ----------------
// Computes xp_out[m0..m0+127][n0..n0+127] = g_x[m0..][0..255] @ W + bias
__device__ __forceinline__ void proj_body(const float* __restrict__ W,
                                          const float* __restrict__ bias,
                                          float* __restrict__ xp_out,
                                          int m0, int n0) {
    __shared__ float As[16][128];
    __shared__ float Bs[16][128];
    int tid = threadIdx.x;
    int tx = tid & 15, ty = tid >> 4;
    float acc[8][8] = {};

    for (int k0 = 0; k0 < 256; k0 += 16) {
        #pragma unroll
        for (int i = 0; i < 2; i++) {
            int fid = tid + i * 256;
            int m   = fid >> 2;
            int kv  = fid & 3;
            float4 v = *reinterpret_cast<const float4*>(
                &g_x[(size_t)(m0 + m) * 256 + k0 + kv * 4]);
            As[kv * 4 + 0][m] = v.x; As[kv * 4 + 1][m] = v.y;
            As[kv * 4 + 2][m] = v.z; As[kv * 4 + 3][m] = v.w;
        }
        #pragma unroll
        for (int i = 0; i < 2; i++) {
            int fid = tid + i * 256;
            int kr  = fid >> 5;
            int nc  = fid & 31;
            *reinterpret_cast<float4*>(&Bs[kr][nc * 4]) =
                *reinterpret_cast<const float4*>(&W[(size_t)(k0 + kr) * NG + n0 + nc * 4]);
        }
        __syncthreads();
        #pragma unroll
        for (int kk = 0; kk < 16; kk++) {
            float a[8], bf[8];
            #pragma unroll
            for (int i = 0; i < 8; i++) a[i]  = As[kk][ty * 8 + i];
            #pragma unroll
            for (int j = 0; j < 8; j++) bf[j] = Bs[kk][tx * 8 + j];
            #pragma unroll
            for (int i = 0; i < 8; i++)
                #pragma unroll
                for (int j = 0; j < 8; j++)
                    acc[i][j] = fmaf(a[i], bf[j], acc[i][j]);
        }
        __syncthreads();
    }
    #pragma unroll
    for (int i = 0; i < 8; i++) {
        size_t m = (size_t)(m0 + ty * 8 + i);
        #pragma unroll
        for (int jv = 0; jv < 2; jv++) {
            float4 o;
            int n = n0 + tx * 8 + jv * 4;
            o.x = acc[i][jv*4+0] + bias[n+0];
            o.y = acc[i][jv*4+1] + bias[n+1];
            o.z = acc[i][jv*4+2] + bias[n+2];
            o.w = acc[i][jv*4+3] + bias[n+3];
            *reinterpret_cast<float4*>(&xp_out[m * NG + n]) = o;
        }
    }
}

// standalone proj (layer 0, after embed)
__global__ __launch_bounds__(256) void proj_kernel(const float* __restrict__ W,
                                                   const float* __restrict__ bias,
                                                   float* __restrict__ xp_out) {
    proj_body(W, bias, xp_out, blockIdx.x * 128, blockIdx.y * 128);
}

// ---------------- scan body ----------------
extern __shared__ float smem[];
__device__ __forceinline__ void scan_body(const float* __restrict__ Wh,
                                          const float* __restrict__ bh,
                                          int layer,
                                          const float* __restrict__ xp,
                                          int sid) {
    float* Wh_s = smem;
    float* h_s  = smem + 24 * WHS;
    float* red  = smem + 24 * WHS + 32 * HSS;
    int cg = sid & 31;
    int bg = sid >> 5;
    int tid = threadIdx.x;
    int u0 = cg * 8;
    int b0 = bg * 32;
    unsigned* bar = g_bar + (layer * T_LEN) * 4 + bg;

    int ks  = tid >> 6;
    int pos = tid & 63;
    int ty2 = pos >> 3;
    int txg = pos & 7;

    int er = tid >> 3;
    int ej = tid & 7;
    int ep = (er >> 2) * 8 + ej;
    int erp = er & 3;

    for (int idx = tid; idx < 24 * 256; idx += 256) {
        int col  = idx >> 8;
        int k    = idx & 255;
        int gate = col >> 3;
        int j    = col & 7;
        Wh_s[col * WHS + k] = Wh[(size_t)k * NG + gate * 256 + u0 + j];
    }
    for (int i = tid; i < 32 * HSS; i += 256) h_s[i] = 0.f;

    float bhz = bh[0 * 256 + u0 + ej];
    float bhr = bh[1 * 256 + u0 + ej];
    float bhh = bh[2 * 256 + u0 + ej];

    const float4* wz4 = reinterpret_cast<const float4*>(&Wh_s[(0 * 8 + txg) * WHS + ks * 64]);
    const float4* wr4 = reinterpret_cast<const float4*>(&Wh_s[(1 * 8 + txg) * WHS + ks * 64]);
    const float4* wh4 = reinterpret_cast<const float4*>(&Wh_s[(2 * 8 + txg) * WHS + ks * 64]);
    const float4* h0_4 = reinterpret_cast<const float4*>(&h_s[(ty2 * 4 + 0) * HSS + ks * 64]);
    const float4* h1_4 = reinterpret_cast<const float4*>(&h_s[(ty2 * 4 + 1) * HSS + ks * 64]);
    const float4* h2_4 = reinterpret_cast<const float4*>(&h_s[(ty2 * 4 + 2) * HSS + ks * 64]);
    const float4* h3_4 = reinterpret_cast<const float4*>(&h_s[(ty2 * 4 + 3) * HSS + ks * 64]);
    float* myred = &red[(ks * 64 + pos) * 12];

    int bglob = b0 + er;
    int u = u0 + ej;

    size_t xb0 = (size_t)bglob * NG;
    float xz = __ldcs(&xp[xb0 + u]);
    float xr = __ldcs(&xp[xb0 + 256 + u]);
    float xh = __ldcs(&xp[xb0 + 512 + u]);
    __syncthreads();

    for (int t = 0; t < T_LEN; t++) {
        float nxz = 0.f, nxr = 0.f, nxh = 0.f;
        if (t + 1 < T_LEN) {
            size_t xb = ((size_t)(t + 1) * B_SZ + bglob) * NG;
            nxz = __ldcs(&xp[xb + u]);
            nxr = __ldcs(&xp[xb + 256 + u]);
            nxh = __ldcs(&xp[xb + 512 + u]);
        }

        float az0=0,az1=0,az2=0,az3=0, ar0=0,ar1=0,ar2=0,ar3=0, ah0=0,ah1=0,ah2=0,ah3=0;
        #pragma unroll 4
        for (int k4 = 0; k4 < 16; k4++) {
            float4 w_z = wz4[k4], w_r = wr4[k4], w_h = wh4[k4];
            float4 v0 = h0_4[k4], v1 = h1_4[k4], v2 = h2_4[k4], v3 = h3_4[k4];
            az0 = fmaf(v0.x,w_z.x,az0); az0 = fmaf(v0.y,w_z.y,az0); az0 = fmaf(v0.z,w_z.z,az0); az0 = fmaf(v0.w,w_z.w,az0);
            az1 = fmaf(v1.x,w_z.x,az1); az1 = fmaf(v1.y,w_z.y,az1); az1 = fmaf(v1.z,w_z.z,az1); az1 = fmaf(v1.w,w_z.w,az1);
            az2 = fmaf(v2.x,w_z.x,az2); az2 = fmaf(v2.y,w_z.y,az2); az2 = fmaf(v2.z,w_z.z,az2); az2 = fmaf(v2.w,w_z.w,az2);
            az3 = fmaf(v3.x,w_z.x,az3); az3 = fmaf(v3.y,w_z.y,az3); az3 = fmaf(v3.z,w_z.z,az3); az3 = fmaf(v3.w,w_z.w,az3);
            ar0 = fmaf(v0.x,w_r.x,ar0); ar0 = fmaf(v0.y,w_r.y,ar0); ar0 = fmaf(v0.z,w_r.z,ar0); ar0 = fmaf(v0.w,w_r.w,ar0);
            ar1 = fmaf(v1.x,w_r.x,ar1); ar1 = fmaf(v1.y,w_r.y,ar1); ar1 = fmaf(v1.z,w_r.z,ar1); ar1 = fmaf(v1.w,w_r.w,ar1);
            ar2 = fmaf(v2.x,w_r.x,ar2); ar2 = fmaf(v2.y,w_r.y,ar2); ar2 = fmaf(v2.z,w_r.z,ar2); ar2 = fmaf(v2.w,w_r.w,ar2);
            ar3 = fmaf(v3.x,w_r.x,ar3); ar3 = fmaf(v3.y,w_r.y,ar3); ar3 = fmaf(v3.z,w_r.z,ar3); ar3 = fmaf(v3.w,w_r.w,ar3);
            ah0 = fmaf(v0.x,w_h.x,ah0); ah0 = fmaf(v0.y,w_h.y,ah0); ah0 = fmaf(v0.z,w_h.z,ah0); ah0 = fmaf(v0.w,w_h.w,ah0);
            ah1 = fmaf(v1.x,w_h.x,ah1); ah1 = fmaf(v1.y,w_h.y,ah1); ah1 = fmaf(v1.z,w_h.z,ah1); ah1 = fmaf(v1.w,w_h.w,ah1);
            ah2 = fmaf(v2.x,w_h.x,ah2); ah2 = fmaf(v2.y,w_h.y,ah2); ah2 = fmaf(v2.z,w_h.z,ah2); ah2 = fmaf(v2.w,w_h.w,ah2);
            ah3 = fmaf(v3.x,w_h.x,ah3); ah3 = fmaf(v3.y,w_h.y,ah3); ah3 = fmaf(v3.z,w_h.z,ah3); ah3 = fmaf(v3.w,w_h.w,ah3);
        }
        {
            float4 s0 = make_float4(az0, ar0, ah0, az1);
            float4 s1 = make_float4(ar1, ah1, az2, ar2);
            float4 s2 = make_float4(ah2, az3, ar3, ah3);
            float4* r4 = reinterpret_cast<float4*>(myred);
            r4[0] = s0; r4[1] = s1; r4[2] = s2;
        }
        __syncthreads();

        float az = bhz, ar = bhr, ah = bhh;
        #pragma unroll
        for (int s = 0; s < 4; s++) {
            const float* rr = &red[(s * 64 + ep) * 12 + erp * 3];
            az += rr[0]; ar += rr[1]; ah += rr[2];
        }

        float hold = h_s[er * HSS + u];
        float z  = __fdividef(1.f, 1.f + __expf(-(xz + az)));
        float r  = __fdividef(1.f, 1.f + __expf(-(xr + ar)));
        float e2 = __expf(2.f * (xh + r * ah));
        float hh = 1.f - __fdividef(2.f, e2 + 1.f);       // tanh
        float hn = z * hold + (1.f - z) * hh;

        int wbuf = (t & 1) ^ 1;
        __stcg(&g_h[wbuf][bglob * 256 + u], hn);
        g_x[((size_t)t * B_SZ + bglob) * 256 + u] = hn;   // must precede release-arrive

        __syncthreads();   // all stores above ordered before tid0's release

        if (tid == 0) {
            unsigned* a = &bar[t * 4];
            asm volatile("red.release.gpu.global.add.u32 [%0], %1;"
                         :: "l"(a), "r"(1u) : "memory");
            if (t < T_LEN - 1) {
                unsigned v;
                do {
                    asm volatile("ld.acquire.gpu.global.u32 %0, [%1];"
                                 : "=r"(v) : "l"(a) : "memory");
                } while (v < BG_CTAS);
            }
        }
        if (t < T_LEN - 1) {
            __syncthreads();
            const float4* hg = reinterpret_cast<const float4*>(&g_h[wbuf][b0 * 256]);
            for (int i = tid; i < 2048; i += 256) {
                float4 v = __ldcg(&hg[i]);
                int row = i >> 6, c = i & 63;
                *reinterpret_cast<float4*>(&h_s[row * HSS + c * 4]) = v;
            }
            __syncthreads();
        }
        xz = nxz; xr = nxr; xh = nxh;
    }
}

// ---------------- fused: scan(l) + gated proj(l+1) ----------------
// bids 0..127: scan CTAs (first wave -> all co-resident, deadlock-free).
// bids 128+ : proj tiles; tile pid -> t = pid/6, n0 = (pid%6)*128. Each waits
// until all 4 bg counters for (layer, t) show 32 arrivals, then reads g_x[t].
__global__ __launch_bounds__(256) void fused_kernel(
    const float* __restrict__ Wh, const float* __restrict__ bh, int layer,
    const float* __restrict__ xp_cur,
    const float* __restrict__ Wx, const float* __restrict__ bx,
    float* __restrict__ xp_next)
{
    if (blockIdx.x < SCAN_CTAS) {
        scan_body(Wh, bh, layer, xp_cur, blockIdx.x);
        return;
    }
    int pid = blockIdx.x - SCAN_CTAS;
    int t   = pid / 6;
    int n0  = (pid % 6) * 128;

    if (threadIdx.x == 0) {
        const unsigned* base = &g_bar[(layer * T_LEN + t) * 4];
        #pragma unroll
        for (int bg = 0; bg < 4; bg++) {
            const unsigned* a = base + bg;
            unsigned v;
            for (;;) {
                asm volatile("ld.acquire.gpu.global.u32 %0, [%1];"
                             : "=r"(v) : "l"(a) : "memory");
                if (v >= BG_CTAS) break;
                __nanosleep(256);
            }
        }
    }
    __syncthreads();
    proj_body(Wx, bx, xp_next, t * 128, n0);
}

// scan-only wrapper (layer 3)
__global__ __launch_bounds__(256) void scan_only_kernel(
    const float* __restrict__ Wh, const float* __restrict__ bh, int layer,
    const float* __restrict__ xp_cur)
{
    scan_body(Wh, bh, layer, xp_cur, blockIdx.x);
}

// ---------------- classifier head ----------------
__global__ void dense_kernel(const float* __restrict__ Wd1, const float* __restrict__ bd1,
                             const float* __restrict__ Wd2, const float* __restrict__ bd2,
                             float* __restrict__ out) {
    __shared__ float xs[256];
    __shared__ float red[256];
    int b = blockIdx.x;
    int j = threadIdx.x;
    xs[j] = g_x[((size_t)(T_LEN - 1) * B_SZ + b) * 256 + j];
    __syncthreads();
    float acc = bd1[j];
    #pragma unroll 8
    for (int k = 0; k < 256; k++) acc = fmaf(xs[k], Wd1[k * 256 + j], acc);
    float h1 = acc > 0.f ? acc : 0.f;
    red[j] = h1 * Wd2[j];
    __syncthreads();
    for (int s = 128; s > 0; s >>= 1) {
        if (j < s) red[j] += red[j + s];
        __syncthreads();
    }
    if (j == 0) out[b] = 1.f / (1.f + expf(-(red[0] + bd2[0])));
}

// ---------------- launch ----------------
extern "C" void kernel_launch(void* const* d_in, const int* in_sizes, int n_in,
                              void* d_out, int out_size) {
    const int*   tokens = (const int*)  d_in[0];
    const float* emb    = (const float*)d_in[1];
    float* out = (float*)d_out;

    void* bar_addr; cudaGetSymbolAddress(&bar_addr, g_bar);
    float* xp0; cudaGetSymbolAddress((void**)&xp0, g_xp0);
    float* xp1; cudaGetSymbolAddress((void**)&xp1, g_xp1);

    const int scan_smem = (24 * WHS + 32 * HSS + 4 * 64 * 12) * (int)sizeof(float); // 70528 B
    cudaFuncSetAttribute(fused_kernel,     cudaFuncAttributeMaxDynamicSharedMemorySize, scan_smem);
    cudaFuncSetAttribute(scan_only_kernel, cudaFuncAttributeMaxDynamicSharedMemorySize, scan_smem);

    cudaMemsetAsync(bar_addr, 0, sizeof(unsigned) * 4 * T_LEN * 4);

    embed_kernel<<<16384, 256>>>(tokens, emb);

    // proj(0): g_x (embeddings) -> xp0
    {
        dim3 pgrid(512, 6);
        proj_kernel<<<pgrid, 256>>>((const float*)d_in[2], (const float*)d_in[4], xp0);
    }

    float* xps[2] = { xp0, xp1 };
    for (int l = 0; l < 3; l++) {
        const float* Wh = (const float*)d_in[3 + 4 * l];
        const float* bh = (const float*)d_in[5 + 4 * l];
        const float* Wxn = (const float*)d_in[2 + 4 * (l + 1)];
        const float* bxn = (const float*)d_in[4 + 4 * (l + 1)];
        fused_kernel<<<SCAN_CTAS + PROJ_CTAS, 256, scan_smem>>>(
            Wh, bh, l, xps[l & 1], Wxn, bxn, xps[(l + 1) & 1]);
    }
    // layer 3: scan only
    scan_only_kernel<<<SCAN_CTAS, 256, scan_smem>>>(
        (const float*)d_in[3 + 12], (const float*)d_in[5 + 12], 3, xps[1]);

    dense_kernel<<<128, 256>>>((const float*)d_in[18], (const float*)d_in[19],
                               (const float*)d_in[20], (const float*)d_in[21], out);
}

// round 5
// speedup vs baseline: 1.0473x; 1.0473x over previous
#include <cuda_runtime.h>
#include <cuda_bf16.h>
#include <math.h>

#define T_LEN 512
#define B_SZ  128
#define NG    768
// scan decomposition: 8 col-groups (32 units) x 16 batch-groups (8 rows)
#define NCG   8
#define NBG   16
#define UC    32           // units per col-group
#define RB    8            // rows per batch-group
#define BG_CTAS 8          // arrivals per batch-group barrier
#define WHS2  260          // Wh_s column stride (floats): 2-way-max weight LDS conflicts
#define HS2   260          // h_s row stride

// ---------------- scratch ----------------
__device__ float    g_x [T_LEN * B_SZ * 256];
__device__ float    g_xp[T_LEN * B_SZ * NG];
__device__ float    g_h [2][B_SZ * 256];
__device__ unsigned g_bar[4 * T_LEN * NBG];      // [layer][t][bg]

// ---------------- embedding ----------------
__global__ void embed_kernel(const int* __restrict__ tokens, const float* __restrict__ emb) {
    int gid = blockIdx.x * blockDim.x + threadIdx.x;
    int row = gid >> 6;
    int c4  = gid & 63;
    int t = row >> 7;
    int b = row & 127;
    int tok = tokens[b * T_LEN + t];
    const float4* e4 = reinterpret_cast<const float4*>(emb);
    float4*       x4 = reinterpret_cast<float4*>(g_x);
    x4[(size_t)row * 64 + c4] = e4[(size_t)tok * 64 + c4];
}

// ---------------- input projection GEMM ----------------
__global__ __launch_bounds__(256) void proj_kernel(const float* __restrict__ W,
                                                   const float* __restrict__ bias) {
    __shared__ float As[16][128];
    __shared__ float Bs[16][128];
    int m0 = blockIdx.x * 128;
    int n0 = blockIdx.y * 128;
    int tid = threadIdx.x;
    int tx = tid & 15, ty = tid >> 4;
    float acc[8][8] = {};

    for (int k0 = 0; k0 < 256; k0 += 16) {
        #pragma unroll
        for (int i = 0; i < 2; i++) {
            int fid = tid + i * 256;
            int m   = fid >> 2;
            int kv  = fid & 3;
            float4 v = *reinterpret_cast<const float4*>(
                &g_x[(size_t)(m0 + m) * 256 + k0 + kv * 4]);
            As[kv * 4 + 0][m] = v.x; As[kv * 4 + 1][m] = v.y;
            As[kv * 4 + 2][m] = v.z; As[kv * 4 + 3][m] = v.w;
        }
        #pragma unroll
        for (int i = 0; i < 2; i++) {
            int fid = tid + i * 256;
            int kr  = fid >> 5;
            int nc  = fid & 31;
            *reinterpret_cast<float4*>(&Bs[kr][nc * 4]) =
                *reinterpret_cast<const float4*>(&W[(size_t)(k0 + kr) * NG + n0 + nc * 4]);
        }
        __syncthreads();
        #pragma unroll
        for (int kk = 0; kk < 16; kk++) {
            float a[8], bf[8];
            #pragma unroll
            for (int i = 0; i < 8; i++) a[i]  = As[kk][ty * 8 + i];
            #pragma unroll
            for (int j = 0; j < 8; j++) bf[j] = Bs[kk][tx * 8 + j];
            #pragma unroll
            for (int i = 0; i < 8; i++)
                #pragma unroll
                for (int j = 0; j < 8; j++)
                    acc[i][j] = fmaf(a[i], bf[j], acc[i][j]);
        }
        __syncthreads();
    }
    #pragma unroll
    for (int i = 0; i < 8; i++) {
        size_t m = (size_t)(m0 + ty * 8 + i);
        #pragma unroll
        for (int jv = 0; jv < 2; jv++) {
            float4 o;
            int n = n0 + tx * 8 + jv * 4;
            o.x = acc[i][jv*4+0] + bias[n+0];
            o.y = acc[i][jv*4+1] + bias[n+1];
            o.z = acc[i][jv*4+2] + bias[n+2];
            o.w = acc[i][jv*4+3] + bias[n+3];
            *reinterpret_cast<float4*>(&g_xp[m * NG + n]) = o;
        }
    }
}

// ---------------- recurrent scan ----------------
// grid 128: sid>>4 = cg (32 units), sid&15 = bg (8 rows).
// GEMM phase: 256 threads = 64 positions (4 row-pairs x 16 unit-pairs) x 4 K-slices.
//   Thread tile: 2 rows x 2 units x 3 gates, K=64. 8 LDS.128 -> 48 FMA per k4.
// Wh_s column layout: c' = gate*32 + up + 16*uin (swizzled for <=2-way LDS conflicts).
// Epilogue: tid = er*32 + ej (8 rows x 32 units), K-partials reduced via smem.
extern __shared__ float smem[];
__global__ __launch_bounds__(256) void scan_kernel(const float* __restrict__ Wh,
                                                   const float* __restrict__ bh,
                                                   int layer) {
    float* Wh_s = smem;                             // [96 c'][WHS2]
    float* h_s  = smem + 96 * WHS2;                 // [8 rows][HS2], cols = global k
    float* red  = smem + 96 * WHS2 + RB * HS2;      // [4 ks][64 pos][12]
    int sid = blockIdx.x;
    int cg = sid >> 4;
    int bg = sid & 15;
    int tid = threadIdx.x;
    int u0 = cg * UC;
    int b0 = bg * RB;
    unsigned* bar = g_bar + (layer * T_LEN) * NBG + bg;

    // GEMM-phase decode
    int ks  = tid >> 6;            // 0..3
    int pos = tid & 63;            // 0..63
    int rp  = pos >> 4;            // row-pair 0..3 (rows rp*2, rp*2+1)
    int up  = pos & 15;            // unit-pair 0..15

    // Epilogue decode
    int er = tid >> 5;             // row 0..7
    int ej = tid & 31;             // unit 0..31
    int epos = (er >> 1) * 16 + (ej >> 1);
    int esub = ((er & 1) * 2 + (ej & 1)) * 3;

    // one-time Wh slice load (96 swizzled columns x 256 k)
    for (int i = tid; i < 96 * 256; i += 256) {
        int k  = i / 96;
        int c  = i - k * 96;               // c' 0..95
        int g  = c >> 5;
        int lo = c & 31;
        int uu = 2 * (lo & 15) + (lo >> 4);
        Wh_s[c * WHS2 + k] = Wh[(size_t)k * NG + g * 256 + u0 + uu];
    }
    for (int i = tid; i < RB * HS2; i += 256) h_s[i] = 0.f;

    float bhz = bh[0 * 256 + u0 + ej];
    float bhr = bh[1 * 256 + u0 + ej];
    float bhh = bh[2 * 256 + u0 + ej];

    // GEMM pointers: weights for (uin=0/1) x gates, h for 2 rows
    const float4* wA[3]; const float4* wB[3];
    #pragma unroll
    for (int g = 0; g < 3; g++) {
        wA[g] = reinterpret_cast<const float4*>(&Wh_s[(g * 32 + up     ) * WHS2 + ks * 64]);
        wB[g] = reinterpret_cast<const float4*>(&Wh_s[(g * 32 + up + 16) * WHS2 + ks * 64]);
    }
    const float4* h0_4 = reinterpret_cast<const float4*>(&h_s[(rp * 2 + 0) * HS2 + ks * 64]);
    const float4* h1_4 = reinterpret_cast<const float4*>(&h_s[(rp * 2 + 1) * HS2 + ks * 64]);
    float* myred = &red[(ks * 64 + pos) * 12];

    int bglob = b0 + er;
    int u = u0 + ej;

    // prologue: xp(t=0)
    size_t xb0 = (size_t)bglob * NG;
    float xz = __ldcs(&g_xp[xb0 + u]);
    float xr = __ldcs(&g_xp[xb0 + 256 + u]);
    float xh = __ldcs(&g_xp[xb0 + 512 + u]);
    __syncthreads();

    for (int t = 0; t < T_LEN; t++) {
        // prefetch xp(t+1)
        float nxz = 0.f, nxr = 0.f, nxh = 0.f;
        if (t + 1 < T_LEN) {
            size_t xb = ((size_t)(t + 1) * B_SZ + bglob) * NG;
            nxz = __ldcs(&g_xp[xb + u]);
            nxr = __ldcs(&g_xp[xb + 256 + u]);
            nxh = __ldcs(&g_xp[xb + 512 + u]);
        }

        // ---- GEMM phase: acc[2 rows][2 units][3 gates], K-slice of 64 ----
        float acc[2][2][3] = {};
        #pragma unroll 4
        for (int k4 = 0; k4 < 16; k4++) {
            float4 v0 = h0_4[k4], v1 = h1_4[k4];
            #pragma unroll
            for (int g = 0; g < 3; g++) {
                float4 a = wA[g][k4];
                float4 b = wB[g][k4];
                acc[0][0][g] = fmaf(v0.x,a.x,acc[0][0][g]); acc[0][0][g] = fmaf(v0.y,a.y,acc[0][0][g]);
                acc[0][0][g] = fmaf(v0.z,a.z,acc[0][0][g]); acc[0][0][g] = fmaf(v0.w,a.w,acc[0][0][g]);
                acc[0][1][g] = fmaf(v0.x,b.x,acc[0][1][g]); acc[0][1][g] = fmaf(v0.y,b.y,acc[0][1][g]);
                acc[0][1][g] = fmaf(v0.z,b.z,acc[0][1][g]); acc[0][1][g] = fmaf(v0.w,b.w,acc[0][1][g]);
                acc[1][0][g] = fmaf(v1.x,a.x,acc[1][0][g]); acc[1][0][g] = fmaf(v1.y,a.y,acc[1][0][g]);
                acc[1][0][g] = fmaf(v1.z,a.z,acc[1][0][g]); acc[1][0][g] = fmaf(v1.w,a.w,acc[1][0][g]);
                acc[1][1][g] = fmaf(v1.x,b.x,acc[1][1][g]); acc[1][1][g] = fmaf(v1.y,b.y,acc[1][1][g]);
                acc[1][1][g] = fmaf(v1.z,b.z,acc[1][1][g]); acc[1][1][g] = fmaf(v1.w,b.w,acc[1][1][g]);
            }
        }
        // store partials: red[ks][pos][(r*2+uin)*3 + g]
        {
            float4 s0 = make_float4(acc[0][0][0], acc[0][0][1], acc[0][0][2], acc[0][1][0]);
            float4 s1 = make_float4(acc[0][1][1], acc[0][1][2], acc[1][0][0], acc[1][0][1]);
            float4 s2 = make_float4(acc[1][0][2], acc[1][1][0], acc[1][1][1], acc[1][1][2]);
            float4* r4 = reinterpret_cast<float4*>(myred);
            r4[0] = s0; r4[1] = s1; r4[2] = s2;
        }
        __syncthreads();

        // ---- epilogue ----
        float az = bhz, ar = bhr, ah = bhh;
        #pragma unroll
        for (int s = 0; s < 4; s++) {
            const float* rr = &red[(s * 64 + epos) * 12 + esub];
            az += rr[0]; ar += rr[1]; ah += rr[2];
        }

        float hold = h_s[er * HS2 + u0 + ej];
        float z  = __fdividef(1.f, 1.f + __expf(-(xz + az)));
        float r  = __fdividef(1.f, 1.f + __expf(-(xr + ar)));
        float e2 = __expf(2.f * (xh + r * ah));
        float hh = 1.f - __fdividef(2.f, e2 + 1.f);       // tanh
        float hn = z * hold + (1.f - z) * hh;

        int wbuf = (t & 1) ^ 1;
        __stcg(&g_h[wbuf][bglob * 256 + u], hn);
        g_x[((size_t)t * B_SZ + bglob) * 256 + u] = hn;   // consumed by next kernel

        __syncthreads();   // h_s reads done + all stcg ordered before tid0's release

        if (t < T_LEN - 1) {
            if (tid == 0) {
                unsigned* a = &bar[t * NBG];
                asm volatile("red.release.gpu.global.add.u32 [%0], %1;"
                             :: "l"(a), "r"(1u) : "memory");
                unsigned v;
                do {
                    asm volatile("ld.acquire.gpu.global.u32 %0, [%1];"
                                 : "=r"(v) : "l"(a) : "memory");
                } while (v < BG_CTAS);
            }
            __syncthreads();
            // reload 8 rows x 256 cols of h (8 KB) from L2
            const float4* hg = reinterpret_cast<const float4*>(&g_h[wbuf][b0 * 256]);
            #pragma unroll
            for (int i = 0; i < 2; i++) {
                int idx = tid + i * 256;          // 0..511
                float4 v = __ldcg(&hg[idx]);
                int row = idx >> 6, c = idx & 63;
                *reinterpret_cast<float4*>(&h_s[row * HS2 + c * 4]) = v;
            }
            __syncthreads();
        }
        xz = nxz; xr = nxr; xh = nxh;
    }
}

// ---------------- classifier head ----------------
__global__ void dense_kernel(const float* __restrict__ Wd1, const float* __restrict__ bd1,
                             const float* __restrict__ Wd2, const float* __restrict__ bd2,
                             float* __restrict__ out) {
    __shared__ float xs[256];
    __shared__ float red[256];
    int b = blockIdx.x;
    int j = threadIdx.x;
    xs[j] = g_x[((size_t)(T_LEN - 1) * B_SZ + b) * 256 + j];
    __syncthreads();
    float acc = bd1[j];
    #pragma unroll 8
    for (int k = 0; k < 256; k++) acc = fmaf(xs[k], Wd1[k * 256 + j], acc);
    float h1 = acc > 0.f ? acc : 0.f;
    red[j] = h1 * Wd2[j];
    __syncthreads();
    for (int s = 128; s > 0; s >>= 1) {
        if (j < s) red[j] += red[j + s];
        __syncthreads();
    }
    if (j == 0) out[b] = 1.f / (1.f + expf(-(red[0] + bd2[0])));
}

// ---------------- launch ----------------
extern "C" void kernel_launch(void* const* d_in, const int* in_sizes, int n_in,
                              void* d_out, int out_size) {
    const int*   tokens = (const int*)  d_in[0];
    const float* emb    = (const float*)d_in[1];
    float* out = (float*)d_out;

    void* bar_addr; cudaGetSymbolAddress(&bar_addr, g_bar);

    const int scan_smem = (96 * WHS2 + RB * HS2 + 4 * 64 * 12) * (int)sizeof(float); // 120448 B
    cudaFuncSetAttribute(scan_kernel, cudaFuncAttributeMaxDynamicSharedMemorySize, scan_smem);

    cudaMemsetAsync(bar_addr, 0, sizeof(unsigned) * 4 * T_LEN * NBG);

    embed_kernel<<<16384, 256>>>(tokens, emb);

    for (int l = 0; l < 4; l++) {
        const float* Wx = (const float*)d_in[2 + 4 * l];
        const float* Wh = (const float*)d_in[3 + 4 * l];
        const float* bx = (const float*)d_in[4 + 4 * l];
        const float* bh = (const float*)d_in[5 + 4 * l];

        dim3 pgrid(512, 6);
        proj_kernel<<<pgrid, 256>>>(Wx, bx);

        scan_kernel<<<128, 256, scan_smem>>>(Wh, bh, l);
    }

    dense_kernel<<<128, 256>>>((const float*)d_in[18], (const float*)d_in[19],
                               (const float*)d_in[20], (const float*)d_in[21], out);
}